// round 14
// baseline (speedup 1.0000x reference)
#include <cuda_runtime.h>
#include <cstdint>

// LSTM_58514634440709: B=8, L=32768, H=96, 2 layers + head.
// R6: 4 clusters x 3 CTAs, TWO sequences per cluster (weights are
// batch-invariant -> one RF-resident copy serves both chains; the second
// chain fills the first chain's latency gaps; barriers/transport amortized).
//   CTA0: layer-0 recurrence (both seqs)   -> h0 stream
//   CTA1: u = W_ih_1 * h0 + b1 (both seqs) -> u stream
//   CTA2: v = W_hh_1 * h1 ; gates ; head   (both seqs)

#define H 96
#define G 384
#define NSEQ 2
#define NPAIR 4          // 8 batches / 2 per cluster
#define NSLOTA 4
#define NSLOTB 2

struct __align__(16) Smem {
    unsigned long long fullA[NSLOTA];
    unsigned long long emptyA[NSLOTA];
    unsigned long long fullB[NSLOTB];
    unsigned long long emptyB[NSLOTB];
    union {
        float ustage[NSLOTB][4][NSEQ][G];   // 24576 B (CTA1 staging)
        float slotB[NSLOTB][4][NSEQ][G];    // CTA2 inbox
    };
    union {
        float hgrp[NSLOTA][4][NSEQ][H];     // 12288 B (CTA0 staging)
        float slotA[NSLOTA][4][NSEQ][H];    // CTA1 inbox
    };
    float hcur[2][NSEQ][H];                 // state ping-pong per seq
    float wpart[NSEQ][2][16];               // CTA2 head partials
    float hwsm[H];                          // head weights (CTA2)
    float xstage[2][NSEQ][4];               // CTA0 x prefetch
};

#define BYTES_A (4 * NSEQ * H * 4)          // 3072
#define BYTES_B (4 * NSEQ * G * 4)          // 12288

__device__ __forceinline__ uint32_t saddr(const void* p) {
    return (uint32_t)__cvta_generic_to_shared(p);
}
__device__ __forceinline__ uint32_t mapa_rank(uint32_t a, uint32_t r) {
    uint32_t d;
    asm("mapa.shared::cluster.u32 %0, %1, %2;" : "=r"(d) : "r"(a), "r"(r));
    return d;
}
__device__ __forceinline__ void mbar_init(uint32_t a, uint32_t cnt) {
    asm volatile("mbarrier.init.shared.b64 [%0], %1;" :: "r"(a), "r"(cnt) : "memory");
}
__device__ __forceinline__ void expect_tx(uint32_t a, uint32_t bytes) {
    asm volatile("mbarrier.arrive.expect_tx.shared.b64 _, [%0], %1;"
                 :: "r"(a), "r"(bytes) : "memory");
}
__device__ __forceinline__ void arrive_remote(uint32_t a) {
    asm volatile("mbarrier.arrive.release.cluster.shared::cluster.b64 _, [%0];"
                 :: "r"(a) : "memory");
}
__device__ __forceinline__ void fence_proxy() {
    asm volatile("fence.proxy.async.shared::cta;" ::: "memory");
}
__device__ __forceinline__ void bulk_s2s(uint32_t dst, uint32_t src,
                                         uint32_t bytes, uint32_t mbar) {
    asm volatile(
        "cp.async.bulk.shared::cluster.shared::cta.mbarrier::complete_tx::bytes "
        "[%0], [%1], %2, [%3];"
        :: "r"(dst), "r"(src), "r"(bytes), "r"(mbar) : "memory");
}
__device__ __forceinline__ void wait_par(uint32_t a, uint32_t par) {
    asm volatile(
        "{\n\t"
        ".reg .pred P;\n\t"
        "WLOOP_%=:\n\t"
        "mbarrier.try_wait.parity.acquire.cluster.shared::cta.b64 P, [%0], %1, 0x989680;\n\t"
        "@P bra WDONE_%=;\n\t"
        "bra WLOOP_%=;\n\t"
        "WDONE_%=:\n\t"
        "}" :: "r"(a), "r"(par) : "memory");
}

#define FMA2(acc, w, h) asm("fma.rn.f32x2 %0, %1, %2, %0;" : "+l"(acc) : "l"(w), "l"(h))
#define ADD2(a, b)      asm("add.rn.f32x2 %0, %0, %1;" : "+l"(a) : "l"(b))

__device__ __forceinline__ float tanhap(float x) {
    float y;
    asm("tanh.approx.f32 %0, %1;" : "=f"(y) : "f"(x));
    return y;
}
__device__ __forceinline__ float lohi_add(unsigned long long a) {
    float lo, hi;
    asm("mov.b64 {%0, %1}, %2;" : "=f"(lo), "=f"(hi) : "l"(a));
    return lo + hi;
}

// Two independent 96-dots with one weight set; interleaved for ILP.
__device__ __forceinline__ void dot96_dual(const unsigned long long* w2,
                                           const float* hA, const float* hB,
                                           float iA, float iB,
                                           float& rA, float& rB) {
    const ulonglong2* a2 = (const ulonglong2*)hA;
    const ulonglong2* b2 = (const ulonglong2*)hB;
    unsigned long long A0 = (unsigned long long)__float_as_uint(iA);
    unsigned long long A1 = 0ull, A2 = 0ull, A3 = 0ull;
    unsigned long long B0 = (unsigned long long)__float_as_uint(iB);
    unsigned long long B1 = 0ull, B2 = 0ull, B3 = 0ull;
#pragma unroll
    for (int kk = 0; kk < 12; kk++) {
        ulonglong2 pa = a2[2 * kk];
        ulonglong2 qa = a2[2 * kk + 1];
        ulonglong2 pb = b2[2 * kk];
        ulonglong2 qb = b2[2 * kk + 1];
        FMA2(A0, w2[4 * kk + 0], pa.x);
        FMA2(B0, w2[4 * kk + 0], pb.x);
        FMA2(A1, w2[4 * kk + 1], pa.y);
        FMA2(B1, w2[4 * kk + 1], pb.y);
        FMA2(A2, w2[4 * kk + 2], qa.x);
        FMA2(B2, w2[4 * kk + 2], qb.x);
        FMA2(A3, w2[4 * kk + 3], qa.y);
        FMA2(B3, w2[4 * kk + 3], qb.y);
    }
    ADD2(A0, A1); ADD2(A2, A3); ADD2(A0, A2);
    ADD2(B0, B1); ADD2(B2, B3); ADD2(B0, B2);
    rA = lohi_add(A0);
    rB = lohi_add(B0);
}

__global__ void __cluster_dims__(3, 1, 1) __launch_bounds__(384, 1)
lstm_pipe_kernel(const float* __restrict__ x,
                 const float* __restrict__ Wih0,
                 const float* __restrict__ Whh0,
                 const float* __restrict__ b0,
                 const float* __restrict__ Wih1,
                 const float* __restrict__ Whh1,
                 const float* __restrict__ b1,
                 const float* __restrict__ h0in,
                 const float* __restrict__ c0in,
                 const float* __restrict__ headw,
                 const float* __restrict__ headb,
                 float* __restrict__ out,
                 int L)
{
    __shared__ Smem sm;
    const int tid = threadIdx.x;
    uint32_t rank;
    asm("mov.u32 %0, %%cluster_ctarank;" : "=r"(rank));
    const int pair = blockIdx.x / 3;          // 2 sequences: 2*pair, 2*pair+1
    const int lane = tid & 31;
    const int w    = tid >> 5;
    const int k    = lane & 7;
    const int g    = lane >> 3;
    const int idx  = w * 8 + k;
    const int row  = g * H + idx;

    if (tid == 0) {
#pragma unroll
        for (int s = 0; s < NSLOTA; s++) {
            mbar_init(saddr(&sm.fullA[s]), 1);
            mbar_init(saddr(&sm.emptyA[s]), 1);
        }
#pragma unroll
        for (int s = 0; s < NSLOTB; s++) {
            mbar_init(saddr(&sm.fullB[s]), 1);
            mbar_init(saddr(&sm.emptyB[s]), 1);
        }
    }

    const float* Wr = (rank == 0) ? (Whh0 + row * H)
                    : (rank == 1) ? (Wih1 + row * H)
                                  : (Whh1 + row * H);
    unsigned long long w2[48];
    {
        const float4* w4 = (const float4*)Wr;
#pragma unroll
        for (int kk = 0; kk < 24; kk++) {
            float4 v = w4[kk];
            w2[2 * kk]     = ((unsigned long long)__float_as_uint(v.y) << 32) | __float_as_uint(v.x);
            w2[2 * kk + 1] = ((unsigned long long)__float_as_uint(v.w) << 32) | __float_as_uint(v.z);
        }
    }
    float bias = (rank == 0) ? b0[row] : (rank == 1) ? b1[row] : 0.f;
    float wx   = (rank == 0) ? Wih0[row] : 0.f;
    float cA = 0.f, cB = 0.f;
    if (g == 0) {
        if (rank == 0) { cA = c0in[idx];     cB = cA; }
        if (rank == 2) { cA = c0in[H + idx]; cB = cA; }
    }
    float hb = (rank == 2) ? headb[0] : 0.f;
    if (tid < H) {
        if (rank == 0) {
            float h0v = h0in[tid];
            sm.hcur[0][0][tid] = h0v;
            sm.hcur[0][1][tid] = h0v;
        }
        if (rank == 2) {
            float h1v = h0in[H + tid];
            sm.hcur[0][0][tid] = h1v;
            sm.hcur[0][1][tid] = h1v;
            sm.hwsm[tid] = headw[tid];
        }
    }
    if (rank == 0) {
        if (tid == 25) {
            float4 x0 = __ldg((const float4*)(x + (2 * pair) * L));
            *(float4*)sm.xstage[0][0] = x0;
        }
        if (tid == 27) {
            float4 x1 = __ldg((const float4*)(x + (2 * pair + 1) * L));
            *(float4*)sm.xstage[0][1] = x1;
        }
    }
    __syncthreads();
    asm volatile("barrier.cluster.arrive.aligned;" ::: "memory");
    asm volatile("barrier.cluster.wait.aligned;" ::: "memory");

    const int ng = L >> 2;

    if (rank == 0) {
        const float* xb0 = x + (2 * pair) * L;
        const float* xb1 = x + (2 * pair + 1) * L;
        uint32_t rSlotA = mapa_rank(saddr(&sm.slotA[0][0][0][0]), 1);
        uint32_t rFullA = mapa_rank(saddr(&sm.fullA[0]), 1);
        uint32_t eA     = saddr(&sm.emptyA[0]);
        for (int gi = 0; gi < ng; gi++) {
            int s = gi & (NSLOTA - 1);
#define L0STEP(j, rb, wb, EXTRAS)                                              \
            {                                                                  \
                float xcA = sm.xstage[gi & 1][0][j];                           \
                float xcB = sm.xstage[gi & 1][1][j];                           \
                float zA, zB;                                                  \
                dot96_dual(w2, sm.hcur[rb][0], sm.hcur[rb][1],                 \
                           __fmaf_rn(xcA, wx, bias),                           \
                           __fmaf_rn(xcB, wx, bias), zA, zB);                  \
                float aA = (g == 2) ? tanhap(zA)                               \
                                    : __fmaf_rn(0.5f, tanhap(0.5f * zA), 0.5f);\
                float aB = (g == 2) ? tanhap(zB)                               \
                                    : __fmaf_rn(0.5f, tanhap(0.5f * zB), 0.5f);\
                float iA = __shfl_sync(0xffffffffu, aA, k);                    \
                float fA = __shfl_sync(0xffffffffu, aA, k + 8);                \
                float gA = __shfl_sync(0xffffffffu, aA, k + 16);               \
                float oA = __shfl_sync(0xffffffffu, aA, k + 24);               \
                float iB = __shfl_sync(0xffffffffu, aB, k);                    \
                float fB = __shfl_sync(0xffffffffu, aB, k + 8);                \
                float gB = __shfl_sync(0xffffffffu, aB, k + 16);               \
                float oB = __shfl_sync(0xffffffffu, aB, k + 24);               \
                EXTRAS                                                         \
                if (g == 0) {                                                  \
                    cA = __fmaf_rn(fA, cA, iA * gA);                           \
                    float hA = oA * tanhap(cA);                                \
                    sm.hcur[wb][0][idx]   = hA;                                \
                    sm.hgrp[s][j][0][idx] = hA;                                \
                    cB = __fmaf_rn(fB, cB, iB * gB);                           \
                    float hB = oB * tanhap(cB);                                \
                    sm.hcur[wb][1][idx]   = hB;                                \
                    sm.hgrp[s][j][1][idx] = hB;                                \
                }                                                              \
                __syncthreads();                                               \
            }
            L0STEP(0, 0, 1,
                if (tid == 25 && gi + 1 < ng) {
                    float4 nx = __ldg((const float4*)(xb0 + 4 * (gi + 1)));
                    *(float4*)sm.xstage[(gi + 1) & 1][0] = nx;
                }
                if (tid == 27 && gi + 1 < ng) {
                    float4 nx = __ldg((const float4*)(xb1 + 4 * (gi + 1)));
                    *(float4*)sm.xstage[(gi + 1) & 1][1] = nx;
                }
                if (tid == 24 && gi > 0) {
                    int ps = (gi - 1) & (NSLOTA - 1);
                    uint32_t pfp = (uint32_t)((gi - 1) >> 2) & 1u;
                    fence_proxy();
                    wait_par(eA + 8u * ps, 1u ^ pfp);
                    bulk_s2s(rSlotA + (uint32_t)BYTES_A * ps,
                             saddr(&sm.hgrp[ps][0][0][0]),
                             BYTES_A, rFullA + 8u * ps);
                }
            )
            L0STEP(1, 1, 0, )
            L0STEP(2, 0, 1, )
            L0STEP(3, 1, 0, )
#undef L0STEP
        }
        if (tid == 24) {
            int ps = (ng - 1) & (NSLOTA - 1);
            uint32_t pfp = (uint32_t)((ng - 1) >> 2) & 1u;
            fence_proxy();
            wait_par(eA + 8u * ps, 1u ^ pfp);
            bulk_s2s(rSlotA + (uint32_t)BYTES_A * ps,
                     saddr(&sm.hgrp[ps][0][0][0]),
                     BYTES_A, rFullA + 8u * ps);
        }
    } else if (rank == 1) {
        uint32_t fA      = saddr(&sm.fullA[0]);
        uint32_t eB      = saddr(&sm.emptyB[0]);
        uint32_t rEmptyA = mapa_rank(saddr(&sm.emptyA[0]), 0);
        uint32_t rSlotB  = mapa_rank(saddr(&sm.slotB[0][0][0][0]), 2);
        uint32_t rFullB  = mapa_rank(saddr(&sm.fullB[0]), 2);
        for (int gi = 0; gi < ng; gi++) {
            int s  = gi & (NSLOTA - 1);
            uint32_t fp = (uint32_t)(gi >> 2) & 1u;
            if (gi > 0) {
                int pg = gi - 1;
                int psA = pg & (NSLOTA - 1);
                int psB = pg & (NSLOTB - 1);
                uint32_t pfpB = (uint32_t)(pg >> 1) & 1u;
                if (tid == 0) arrive_remote(rEmptyA + 8u * psA);
                if (tid == 32) {
                    fence_proxy();
                    wait_par(eB + 8u * psB, 1u ^ pfpB);
                    bulk_s2s(rSlotB + (uint32_t)BYTES_B * psB,
                             saddr(&sm.ustage[psB][0][0][0]),
                             BYTES_B, rFullB + 8u * psB);
                }
            }
            if (tid == 64) expect_tx(fA + 8u * s, BYTES_A);
            wait_par(fA + 8u * s, fp);
            int sB = gi & (NSLOTB - 1);
#pragma unroll
            for (int j = 0; j < 4; j++) {
                float u0, u1;
                dot96_dual(w2, sm.slotA[s][j][0], sm.slotA[s][j][1],
                           bias, bias, u0, u1);
                sm.ustage[sB][j][0][row] = u0;
                sm.ustage[sB][j][1][row] = u1;
            }
            __syncthreads();
        }
        if (tid == 32) {
            int pg = ng - 1;
            int psB = pg & (NSLOTB - 1);
            uint32_t pfpB = (uint32_t)(pg >> 1) & 1u;
            fence_proxy();
            wait_par(eB + 8u * psB, 1u ^ pfpB);
            bulk_s2s(rSlotB + (uint32_t)BYTES_B * psB,
                     saddr(&sm.ustage[psB][0][0][0]),
                     BYTES_B, rFullB + 8u * psB);
        }
    } else {
        uint32_t fB      = saddr(&sm.fullB[0]);
        uint32_t rEmptyB = mapa_rank(saddr(&sm.emptyB[0]), 1);
        float* yb0 = out + (2 * pair) * L;
        float* yb1 = out + (2 * pair + 1) * L;
        for (int gi = 0; gi < ng; gi++) {
            int s = gi & (NSLOTB - 1);
            uint32_t fp = (uint32_t)(gi >> 1) & 1u;
            if (tid == 0 && gi > 0)
                arrive_remote(rEmptyB + 8u * ((gi - 1) & (NSLOTB - 1)));
            if (tid == 64) expect_tx(fB + 8u * s, BYTES_B);
#define L2STEP(j, rb, wb)                                                      \
            {                                                                  \
                int t = 4 * gi + j;                                            \
                float vA, vB, zA, zB;                                          \
                if (j == 0) {                                                  \
                    dot96_dual(w2, sm.hcur[rb][0], sm.hcur[rb][1],             \
                               0.f, 0.f, vA, vB);                              \
                    wait_par(fB + 8u * s, fp);                                 \
                    zA = vA + sm.slotB[s][0][0][row];                          \
                    zB = vB + sm.slotB[s][0][1][row];                          \
                } else {                                                       \
                    dot96_dual(w2, sm.hcur[rb][0], sm.hcur[rb][1],             \
                               sm.slotB[s][j][0][row],                         \
                               sm.slotB[s][j][1][row], zA, zB);                \
                }                                                              \
                float aA = (g == 2) ? tanhap(zA)                               \
                                    : __fmaf_rn(0.5f, tanhap(0.5f * zA), 0.5f);\
                float aB = (g == 2) ? tanhap(zB)                               \
                                    : __fmaf_rn(0.5f, tanhap(0.5f * zB), 0.5f);\
                float iA = __shfl_sync(0xffffffffu, aA, k);                    \
                float fAg = __shfl_sync(0xffffffffu, aA, k + 8);               \
                float gA = __shfl_sync(0xffffffffu, aA, k + 16);               \
                float oA = __shfl_sync(0xffffffffu, aA, k + 24);               \
                float iB = __shfl_sync(0xffffffffu, aB, k);                    \
                float fBg = __shfl_sync(0xffffffffu, aB, k + 8);               \
                float gB = __shfl_sync(0xffffffffu, aB, k + 16);               \
                float oB = __shfl_sync(0xffffffffu, aB, k + 24);               \
                if (g == 0) {                                                  \
                    cA = __fmaf_rn(fAg, cA, iA * gA);                          \
                    float hA = oA * tanhap(cA);                                \
                    sm.hcur[wb][0][idx] = hA;                                  \
                    cB = __fmaf_rn(fBg, cB, iB * gB);                          \
                    float hB = oB * tanhap(cB);                                \
                    sm.hcur[wb][1][idx] = hB;                                  \
                }                                                              \
                if (lane == 25 && t >= 1) {                                    \
                    const float4* hpp = (const float4*)&sm.hcur[rb][0][8 * w]; \
                    const float4* wpp = (const float4*)&sm.hwsm[8 * w];        \
                    float4 hA4 = hpp[0], hB4 = hpp[1];                         \
                    float4 wA4 = wpp[0], wB4 = wpp[1];                         \
                    float p = hA4.x * wA4.x + hA4.y * wA4.y + hA4.z * wA4.z    \
                            + hA4.w * wA4.w + hB4.x * wB4.x + hB4.y * wB4.y    \
                            + hB4.z * wB4.z + hB4.w * wB4.w;                   \
                    sm.wpart[0][(t - 1) & 1][w] = p;                           \
                }                                                              \
                if (lane == 27 && t >= 1) {                                    \
                    const float4* hpp = (const float4*)&sm.hcur[rb][1][8 * w]; \
                    const float4* wpp = (const float4*)&sm.hwsm[8 * w];        \
                    float4 hA4 = hpp[0], hB4 = hpp[1];                         \
                    float4 wA4 = wpp[0], wB4 = wpp[1];                         \
                    float p = hA4.x * wA4.x + hA4.y * wA4.y + hA4.z * wA4.z    \
                            + hA4.w * wA4.w + hB4.x * wB4.x + hB4.y * wB4.y    \
                            + hB4.z * wB4.z + hB4.w * wB4.w;                   \
                    sm.wpart[1][(t - 1) & 1][w] = p;                           \
                }                                                              \
                if (tid == 26 && t >= 2) {                                     \
                    const float4* qq = (const float4*)sm.wpart[0][t & 1];      \
                    float4 qa = qq[0], qb = qq[1], qc = qq[2];                 \
                    yb0[t - 2] = hb + qa.x + qa.y + qa.z + qa.w                \
                                    + qb.x + qb.y + qb.z + qb.w                \
                                    + qc.x + qc.y + qc.z + qc.w;               \
                }                                                              \
                if (tid == 30 && t >= 2) {                                     \
                    const float4* qq = (const float4*)sm.wpart[1][t & 1];      \
                    float4 qa = qq[0], qb = qq[1], qc = qq[2];                 \
                    yb1[t - 2] = hb + qa.x + qa.y + qa.z + qa.w                \
                                    + qb.x + qb.y + qb.z + qb.w                \
                                    + qc.x + qc.y + qc.z + qc.w;               \
                }                                                              \
                __syncthreads();                                               \
            }
            L2STEP(0, 0, 1)
            L2STEP(1, 1, 0)
            L2STEP(2, 0, 1)
            L2STEP(3, 1, 0)
#undef L2STEP
        }
        // drain: partials for h(L-1) (in hcur[0]), then y(L-2), y(L-1)
        if (lane == 25) {
            const float4* hpp = (const float4*)&sm.hcur[0][0][8 * w];
            const float4* wpp = (const float4*)&sm.hwsm[8 * w];
            float4 hA4 = hpp[0], hB4 = hpp[1];
            float4 wA4 = wpp[0], wB4 = wpp[1];
            float p = hA4.x * wA4.x + hA4.y * wA4.y + hA4.z * wA4.z
                    + hA4.w * wA4.w + hB4.x * wB4.x + hB4.y * wB4.y
                    + hB4.z * wB4.z + hB4.w * wB4.w;
            sm.wpart[0][1][w] = p;
        }
        if (lane == 27) {
            const float4* hpp = (const float4*)&sm.hcur[0][1][8 * w];
            const float4* wpp = (const float4*)&sm.hwsm[8 * w];
            float4 hA4 = hpp[0], hB4 = hpp[1];
            float4 wA4 = wpp[0], wB4 = wpp[1];
            float p = hA4.x * wA4.x + hA4.y * wA4.y + hA4.z * wA4.z
                    + hA4.w * wA4.w + hB4.x * wB4.x + hB4.y * wB4.y
                    + hB4.z * wB4.z + hB4.w * wB4.w;
            sm.wpart[1][1][w] = p;
        }
        if (tid == 26) {
            const float4* qq = (const float4*)sm.wpart[0][0];
            float4 qa = qq[0], qb = qq[1], qc = qq[2];
            yb0[L - 2] = hb + qa.x + qa.y + qa.z + qa.w
                            + qb.x + qb.y + qb.z + qb.w
                            + qc.x + qc.y + qc.z + qc.w;
        }
        if (tid == 30) {
            const float4* qq = (const float4*)sm.wpart[1][0];
            float4 qa = qq[0], qb = qq[1], qc = qq[2];
            yb1[L - 2] = hb + qa.x + qa.y + qa.z + qa.w
                            + qb.x + qb.y + qb.z + qb.w
                            + qc.x + qc.y + qc.z + qc.w;
        }
        __syncthreads();
        if (tid == 26) {
            const float4* qq = (const float4*)sm.wpart[0][1];
            float4 qa = qq[0], qb = qq[1], qc = qq[2];
            yb0[L - 1] = hb + qa.x + qa.y + qa.z + qa.w
                            + qb.x + qb.y + qb.z + qb.w
                            + qc.x + qc.y + qc.z + qc.w;
        }
        if (tid == 30) {
            const float4* qq = (const float4*)sm.wpart[1][1];
            float4 qa = qq[0], qb = qq[1], qc = qq[2];
            yb1[L - 1] = hb + qa.x + qa.y + qa.z + qa.w
                            + qb.x + qb.y + qb.z + qb.w
                            + qc.x + qc.y + qc.z + qc.w;
        }
    }

    asm volatile("barrier.cluster.arrive.aligned;" ::: "memory");
    asm volatile("barrier.cluster.wait.aligned;" ::: "memory");
}

extern "C" void kernel_launch(void* const* d_in, const int* in_sizes, int n_in,
                              void* d_out, int out_size) {
    const float* x     = (const float*)d_in[0];
    const float* Wih0  = (const float*)d_in[1];
    const float* Whh0  = (const float*)d_in[2];
    const float* b0    = (const float*)d_in[3];
    const float* Wih1  = (const float*)d_in[4];
    const float* Whh1  = (const float*)d_in[5];
    const float* b1    = (const float*)d_in[6];
    const float* h0in  = (const float*)d_in[7];
    const float* c0in  = (const float*)d_in[8];
    const float* headw = (const float*)d_in[9];
    const float* headb = (const float*)d_in[10];
    float* out = (float*)d_out;
    int L = in_sizes[0] / 8;

    lstm_pipe_kernel<<<NPAIR * 3, 384>>>(x, Wih0, Whh0, b0, Wih1, Whh1, b1,
                                         h0in, c0in, headw, headb, out, L);
}